// round 10
// baseline (speedup 1.0000x reference)
#include <cuda_runtime.h>

#define BATCH   16
#define EPSV    1e-5f
#define SLICES  128              // blocks per batch segment
#define TPB     256
#define STRIDE  (SLICES * TPB)   // quad stride per segment sweep

// Global scratch (allocation-free: __device__ arrays)
__device__ float g_sum[BATCH * 16];
__device__ float g_ssq[BATCH * 16];
__device__ int   g_start[BATCH + 1]; // segment starts in sorted batch_id

// Setup: zero accumulators + boundary detection on the sorted batch_id.
// Loop-free per thread: one int4 load (4 ids) + one scalar edge load, all
// independent -> no loop-carried scoreboard drain.
__global__ void ogn_setup_kernel(const int* __restrict__ batch_id, int nrows) {
    const int t   = threadIdx.x;
    const int tid = blockIdx.x * blockDim.x + t;

    if (blockIdx.x == 0) {
        g_sum[t] = 0.f;                      // TPB == 256 == BATCH*16
        g_ssq[t] = 0.f;
        if (t == 0) {
            g_start[0] = 0;
            int bfirst = __ldg(&batch_id[0]);
            for (int v = 1; v <= bfirst; v++) g_start[v] = 0;           // leading empties
            int blast = __ldg(&batch_id[nrows - 1]);
            for (int v = blast + 1; v <= BATCH; v++) g_start[v] = nrows; // trailing empties
        }
    }

    const int i0 = tid * 4;                  // this thread's 4-element window
    if (i0 >= nrows - 1) return;

    int e[5];
    if (i0 + 4 < nrows) {                    // fast path: int4 + scalar edge
        int4 v = __ldg(&((const int4*)batch_id)[tid]);
        e[0] = v.x; e[1] = v.y; e[2] = v.z; e[3] = v.w;
        e[4] = __ldg(&batch_id[i0 + 4]);
        #pragma unroll
        for (int j = 0; j < 4; j++) {
            if (e[j] != e[j + 1]) {
                for (int v2 = e[j] + 1; v2 <= e[j + 1]; v2++) g_start[v2] = i0 + j + 1;
            }
        }
    } else {                                 // ragged tail (nrows not mult of 4)
        for (int i = i0; i < nrows - 1; i++) {
            int a = __ldg(&batch_id[i]);
            int b = __ldg(&batch_id[i + 1]);
            if (a != b) {
                for (int v2 = a + 1; v2 <= b; v2++) g_start[v2] = i + 1;
            }
        }
    }
}

// Pass 1: per-(batch, group) sum / sum-of-squares.
// Vector accumulators (4 independent FADD chains + 4 independent FFMA chains
// per accumulator pair) + 4 hand-batched independent __ldcg loads per
// iteration -> ~16 loads in flight per thread (the prior scalar-reduction
// version serialized consumption and ran at only 4.9 TB/s on a pure read).
// __ldcg: L2-only (populates L2 for pass2's reverse-sweep reuse, skips L1).
__global__ void __launch_bounds__(TPB)
ogn_pass1_kernel(const float4* __restrict__ data4) {
    const int t     = threadIdx.x;
    const int g     = t & 15;
    const int b     = blockIdx.x & (BATCH - 1);
    const int slice = blockIdx.x >> 4;

    const int qlim = g_start[b + 1] * 16;
    int qi = g_start[b] * 16 + slice * TPB + t;

    float4 s0 = make_float4(0.f, 0.f, 0.f, 0.f);
    float4 s1 = make_float4(0.f, 0.f, 0.f, 0.f);
    float4 p0 = make_float4(0.f, 0.f, 0.f, 0.f);
    float4 p1 = make_float4(0.f, 0.f, 0.f, 0.f);

    for (; qi + 3 * STRIDE < qlim; qi += 4 * STRIDE) {
        float4 v0 = __ldcg(&data4[qi]);
        float4 v1 = __ldcg(&data4[qi + STRIDE]);
        float4 v2 = __ldcg(&data4[qi + 2 * STRIDE]);
        float4 v3 = __ldcg(&data4[qi + 3 * STRIDE]);
        s0.x += v0.x; s0.y += v0.y; s0.z += v0.z; s0.w += v0.w;
        p0.x = fmaf(v0.x, v0.x, p0.x); p0.y = fmaf(v0.y, v0.y, p0.y);
        p0.z = fmaf(v0.z, v0.z, p0.z); p0.w = fmaf(v0.w, v0.w, p0.w);
        s1.x += v1.x; s1.y += v1.y; s1.z += v1.z; s1.w += v1.w;
        p1.x = fmaf(v1.x, v1.x, p1.x); p1.y = fmaf(v1.y, v1.y, p1.y);
        p1.z = fmaf(v1.z, v1.z, p1.z); p1.w = fmaf(v1.w, v1.w, p1.w);
        s0.x += v2.x; s0.y += v2.y; s0.z += v2.z; s0.w += v2.w;
        p0.x = fmaf(v2.x, v2.x, p0.x); p0.y = fmaf(v2.y, v2.y, p0.y);
        p0.z = fmaf(v2.z, v2.z, p0.z); p0.w = fmaf(v2.w, v2.w, p0.w);
        s1.x += v3.x; s1.y += v3.y; s1.z += v3.z; s1.w += v3.w;
        p1.x = fmaf(v3.x, v3.x, p1.x); p1.y = fmaf(v3.y, v3.y, p1.y);
        p1.z = fmaf(v3.z, v3.z, p1.z); p1.w = fmaf(v3.w, v3.w, p1.w);
    }
    for (; qi < qlim; qi += STRIDE) {         // <= 3 stragglers
        float4 v = __ldcg(&data4[qi]);
        s0.x += v.x; s0.y += v.y; s0.z += v.z; s0.w += v.w;
        p0.x = fmaf(v.x, v.x, p0.x); p0.y = fmaf(v.y, v.y, p0.y);
        p0.z = fmaf(v.z, v.z, p0.z); p0.w = fmaf(v.w, v.w, p0.w);
    }

    float gsum = ((s0.x + s1.x) + (s0.y + s1.y)) + ((s0.z + s1.z) + (s0.w + s1.w));
    float gssq = ((p0.x + p1.x) + (p0.y + p1.y)) + ((p0.z + p1.z) + (p0.w + p1.w));

    // lanes t and t+16 in each warp share g: fold, then cross-warp via shared.
    gsum += __shfl_xor_sync(0xffffffffu, gsum, 16);
    gssq += __shfl_xor_sync(0xffffffffu, gssq, 16);

    __shared__ float sh_sum[8][16];
    __shared__ float sh_ssq[8][16];
    const int w = t >> 5;
    if ((t & 31) < 16) { sh_sum[w][g] = gsum; sh_ssq[w][g] = gssq; }
    __syncthreads();

    if (t < 16) {
        float s = 0.f, q = 0.f;
        #pragma unroll
        for (int i = 0; i < 8; i++) { s += sh_sum[i][t]; q += sh_ssq[i][t]; }
        if (s != 0.f || q != 0.f) {
            atomicAdd(&g_sum[b * 16 + t], s);
            atomicAdd(&g_ssq[b * 16 + t], q);
        }
    }
}

// Pass 2: out = x * A[b][c] + B[b][c].
// Inline per-block stats -> register A/B, then a REVERSE sweep of this
// segment so the lines pass1 just left in L2 are consumed first.
// __ldcs/__stcs keep both streams evict-first.
__global__ void __launch_bounds__(TPB)
ogn_pass2_kernel(const float4* __restrict__ data4,
                 float4* __restrict__ out4,
                 const float* __restrict__ weights,
                 const float* __restrict__ bias) {
    __shared__ float smean[16], sistd[16];
    const int t     = threadIdx.x;
    const int g     = t & 15;
    const int b     = blockIdx.x & (BATCH - 1);
    const int slice = blockIdx.x >> 4;

    const int r0 = g_start[b];
    const int r1 = g_start[b + 1];

    if (t < 16) {
        float n = (float)(r1 - r0);
        float inv_count = 1.f / (n * 4.f + EPSV);
        float s = g_sum[b * 16 + t], q = g_ssq[b * 16 + t];
        float m = s * inv_count;
        float var = (q - 2.f * m * s + 4.f * n * m * m) * inv_count;
        smean[t] = m;
        sistd[t] = rsqrtf(var + EPSV);
    }
    __syncthreads();

    const float4 w4  = __ldg(&((const float4*)weights)[g]);
    const float4 bi4 = __ldg(&((const float4*)bias)[g]);
    const float istd = sistd[g];
    const float m    = smean[g];
    float4 a, bb;
    a.x = istd * w4.x;  a.y = istd * w4.y;  a.z = istd * w4.z;  a.w = istd * w4.w;
    bb.x = bi4.x - m * a.x;  bb.y = bi4.y - m * a.y;
    bb.z = bi4.z - m * a.z;  bb.w = bi4.w - m * a.w;

    const int base = r0 * 16 + slice * TPB + t;
    const int span = r1 * 16 - base;
    if (span > 0) {
        const int kmax = (span + STRIDE - 1) / STRIDE;   // STRIDE is pow2 -> shift
        #pragma unroll 4
        for (int k = kmax - 1; k >= 0; --k) {
            const int qi = base + k * STRIDE;
            float4 v = __ldcs(&data4[qi]);
            float4 o;
            o.x = fmaf(v.x, a.x, bb.x);
            o.y = fmaf(v.y, a.y, bb.y);
            o.z = fmaf(v.z, a.z, bb.z);
            o.w = fmaf(v.w, a.w, bb.w);
            __stcs(&out4[qi], o);
        }
    }
}

extern "C" void kernel_launch(void* const* d_in, const int* in_sizes, int n_in,
                              void* d_out, int out_size) {
    const float* data     = (const float*)d_in[0];
    const int*   batch_id = (const int*)d_in[1];
    const float* weights  = (const float*)d_in[2];
    const float* bias     = (const float*)d_in[3];
    float*       out      = (float*)d_out;
    const int    nrows    = in_sizes[1];          // batch_id element count = N

    const int setup_blocks = (nrows / 4 + TPB - 1) / TPB + 1;  // ~1025 for N=1M
    ogn_setup_kernel<<<setup_blocks, TPB>>>(batch_id, nrows);
    ogn_pass1_kernel<<<BATCH * SLICES, TPB>>>((const float4*)data);
    ogn_pass2_kernel<<<BATCH * SLICES, TPB>>>((const float4*)data, (float4*)out,
                                              weights, bias);
}